// round 10
// baseline (speedup 1.0000x reference)
#include <cuda_runtime.h>
#include <cuda_bf16.h>
#include <cstdint>
#include <math.h>

// Problem constants
#define BB 4
#define LL 512
#define DM 256
#define NL 6
#define DI 512
#define DS 16
#define DC 4
#define DTR 16
#define TT (BB * LL)        // 2048 tokens
#define XZW (2 * DI)        // 1024
#define RXW (DTR + 2 * DS)  // 48
#define XSPLIT 4            // split-K factor for x-proj

// ---------------------------------------------------------------------------
// Scratch (device globals; no allocation allowed)
// ---------------------------------------------------------------------------
__device__ __align__(16) float g_scale[TT];
__device__ __align__(16) float g_xz[TT * XZW];
__device__ __align__(16) float g_u[TT * DI];
__device__ __align__(16) float g_xdbc[XSPLIT * TT * RXW];   // K-split partials
__device__ __align__(16) float g_yg[TT * DI];

// ---------------------------------------------------------------------------
// RMSNorm scale: scale[t] = rsqrt(mean(x[t]^2)+eps). One warp per token.
// ---------------------------------------------------------------------------
__global__ void rms_scale_kernel(const float* __restrict__ x,
                                 float* __restrict__ scale) {
    int w = (blockIdx.x * blockDim.x + threadIdx.x) >> 5;
    int lane = threadIdx.x & 31;
    const float* xp = x + (size_t)w * DM + lane * 8;
    float4 a = *(const float4*)xp;
    float4 b = *(const float4*)(xp + 4);
    float sq = a.x*a.x + a.y*a.y + a.z*a.z + a.w*a.w
             + b.x*b.x + b.y*b.y + b.z*b.z + b.w*b.w;
#pragma unroll
    for (int o = 16; o > 0; o >>= 1) sq += __shfl_xor_sync(0xffffffffu, sq, o);
    if (lane == 0) scale[w] = rsqrtf(sq / (float)DM + 1e-5f);
}

// ---------------------------------------------------------------------------
// SIMT TN GEMM, double-buffered, 128x64 tile, 8x4 per thread, BK=16.
// C[m,n] = sum_{k in chunk} (A[m,k]*arow[m]*acol[k]) * Bw[n,k]  (+bias[n])
// mode 0: direct store (+bias)
// mode 1: store to C + z*M*N (per-split partial output)
// mode 2: atomicAdd into C (+bias only from split z==0)
// A: [M,K] fp32 rm; Bw: [N,K] fp32 rm. M%128==0, kchunk%16==0.
// ---------------------------------------------------------------------------
__global__ void __launch_bounds__(256, 2)
gemm_tn_kernel(const float* __restrict__ A, const float* __restrict__ Bw,
               const float* __restrict__ bias,
               const float* __restrict__ arow, const float* __restrict__ acol,
               float* __restrict__ C, int M, int N, int K,
               int kchunk, int mode) {
    __shared__ float As[2][16][132];
    __shared__ float Bs[2][16][68];
    int tid = threadIdx.x;
    int m0 = blockIdx.y * 128;
    int n0 = blockIdx.x * 64;
    int kbeg = blockIdx.z * kchunk;
    int kend = kbeg + kchunk;
    int nt = N - n0; if (nt > 64) nt = 64;

    // loaders
    int lrow = tid >> 1;          // A row 0..127
    int lcol = (tid & 1) * 8;     // A col 0 or 8
    int brow = tid >> 2;          // B row 0..63
    int bcol = (tid & 3) * 4;     // B col 0,4,8,12
    float rs = arow ? arow[m0 + lrow] : 1.f;
    const float* ap = A + (size_t)(m0 + lrow) * K + lcol;
    const float* bp = Bw + (size_t)(n0 + brow) * K + bcol;
    bool bvalid = brow < nt;

    int tx = tid & 15;            // n: 16 x 4
    int ty = tid >> 4;            // m: 16 x 8

    float acc[8][4];
#pragma unroll
    for (int i = 0; i < 8; i++)
#pragma unroll
        for (int j = 0; j < 4; j++) acc[i][j] = 0.f;

    float4 sa0, sa1, sb0;
    // prefetch first tile
    {
        sa0 = *(const float4*)(ap + kbeg);
        sa1 = *(const float4*)(ap + kbeg + 4);
        if (acol) {
            float4 w0 = *(const float4*)(acol + kbeg + lcol);
            float4 w1 = *(const float4*)(acol + kbeg + lcol + 4);
            sa0.x *= w0.x; sa0.y *= w0.y; sa0.z *= w0.z; sa0.w *= w0.w;
            sa1.x *= w1.x; sa1.y *= w1.y; sa1.z *= w1.z; sa1.w *= w1.w;
        }
        sa0.x *= rs; sa0.y *= rs; sa0.z *= rs; sa0.w *= rs;
        sa1.x *= rs; sa1.y *= rs; sa1.z *= rs; sa1.w *= rs;
        sb0 = bvalid ? *(const float4*)(bp + kbeg) : make_float4(0.f,0.f,0.f,0.f);
    }
    int buf = 0;
    // store tile 0
    As[0][lcol+0][lrow]=sa0.x; As[0][lcol+1][lrow]=sa0.y;
    As[0][lcol+2][lrow]=sa0.z; As[0][lcol+3][lrow]=sa0.w;
    As[0][lcol+4][lrow]=sa1.x; As[0][lcol+5][lrow]=sa1.y;
    As[0][lcol+6][lrow]=sa1.z; As[0][lcol+7][lrow]=sa1.w;
    Bs[0][bcol+0][brow]=sb0.x; Bs[0][bcol+1][brow]=sb0.y;
    Bs[0][bcol+2][brow]=sb0.z; Bs[0][bcol+3][brow]=sb0.w;
    __syncthreads();

    for (int k0 = kbeg; k0 < kend; k0 += 16) {
        bool more = (k0 + 16) < kend;
        if (more) {
            int kn = k0 + 16;
            sa0 = *(const float4*)(ap + kn);
            sa1 = *(const float4*)(ap + kn + 4);
            if (acol) {
                float4 w0 = *(const float4*)(acol + kn + lcol);
                float4 w1 = *(const float4*)(acol + kn + lcol + 4);
                sa0.x *= w0.x; sa0.y *= w0.y; sa0.z *= w0.z; sa0.w *= w0.w;
                sa1.x *= w1.x; sa1.y *= w1.y; sa1.z *= w1.z; sa1.w *= w1.w;
            }
            sa0.x *= rs; sa0.y *= rs; sa0.z *= rs; sa0.w *= rs;
            sa1.x *= rs; sa1.y *= rs; sa1.z *= rs; sa1.w *= rs;
            sb0 = bvalid ? *(const float4*)(bp + kn) : make_float4(0.f,0.f,0.f,0.f);
        }
#pragma unroll
        for (int kk = 0; kk < 16; kk++) {
            float4 a0 = *(float4*)&As[buf][kk][ty * 8];
            float4 a1 = *(float4*)&As[buf][kk][ty * 8 + 4];
            float4 b0 = *(float4*)&Bs[buf][kk][tx * 4];
            float a[8] = {a0.x,a0.y,a0.z,a0.w,a1.x,a1.y,a1.z,a1.w};
            float b[4] = {b0.x,b0.y,b0.z,b0.w};
#pragma unroll
            for (int i = 0; i < 8; i++)
#pragma unroll
                for (int j = 0; j < 4; j++)
                    acc[i][j] = fmaf(a[i], b[j], acc[i][j]);
        }
        if (more) {
            buf ^= 1;
            As[buf][lcol+0][lrow]=sa0.x; As[buf][lcol+1][lrow]=sa0.y;
            As[buf][lcol+2][lrow]=sa0.z; As[buf][lcol+3][lrow]=sa0.w;
            As[buf][lcol+4][lrow]=sa1.x; As[buf][lcol+5][lrow]=sa1.y;
            As[buf][lcol+6][lrow]=sa1.z; As[buf][lcol+7][lrow]=sa1.w;
            Bs[buf][bcol+0][brow]=sb0.x; Bs[buf][bcol+1][brow]=sb0.y;
            Bs[buf][bcol+2][brow]=sb0.z; Bs[buf][bcol+3][brow]=sb0.w;
            __syncthreads();
        }
    }

    // epilogue
    if (mode == 2) {
        const float* bb = (blockIdx.z == 0) ? bias : nullptr;
#pragma unroll
        for (int i = 0; i < 8; i++) {
            int gm = m0 + ty * 8 + i;
#pragma unroll
            for (int j = 0; j < 4; j++) {
                int gn = n0 + tx * 4 + j;
                if (gn - n0 >= nt) continue;
                float v = acc[i][j];
                if (bb) v += bb[gn];
                atomicAdd(&C[(size_t)gm * N + gn], v);
            }
        }
    } else {
        float* Cp = C + (mode == 1 ? (size_t)blockIdx.z * M * N : 0);
        int colb = tx * 4;
        if (colb < nt) {
            float4 bv = make_float4(0.f,0.f,0.f,0.f);
            if (bias) bv = *(const float4*)(bias + n0 + colb);
#pragma unroll
            for (int i = 0; i < 8; i++) {
                int gm = m0 + ty * 8 + i;
                float4 v = make_float4(acc[i][0]+bv.x, acc[i][1]+bv.y,
                                       acc[i][2]+bv.z, acc[i][3]+bv.w);
                *(float4*)(Cp + (size_t)gm * N + n0 + colb) = v;
            }
        }
    }
}

// ---------------------------------------------------------------------------
// Causal depthwise conv (width 4) + SiLU. xz layout [t, 1024]; xin = first 512.
// ---------------------------------------------------------------------------
__global__ void conv_silu_kernel(const float* __restrict__ xz,
                                 const float* __restrict__ cw,
                                 float* __restrict__ u) {
    int idx = blockIdx.x * blockDim.x + threadIdx.x;
    int t = idx >> 9;
    int d = idx & 511;
    int l = t & 511;
    float acc = 0.f;
#pragma unroll
    for (int j = 0; j < 4; j++) {
        int ll = l - 3 + j;
        if (ll >= 0) acc = fmaf(cw[d * 4 + j], xz[(size_t)(t - 3 + j) * XZW + d], acc);
    }
    float s = 1.f / (1.f + __expf(-acc));
    u[idx] = acc * s;
}

// ---------------------------------------------------------------------------
// Fused scan: inline K-split reduction of xdbc partials, inline delta
// (dt-proj + softplus via 16-lane shfl dot), recurrence, inline gate.
// Thread = (b, d, n). 16-lane groups share d.
// ---------------------------------------------------------------------------
__global__ void scan_fused_kernel(const float* __restrict__ xp,  // [4][TT][48]
                                  const float* __restrict__ u,
                                  const float* __restrict__ xz,
                                  const float* __restrict__ A_log,
                                  const float* __restrict__ dtw,
                                  const float* __restrict__ dtb,
                                  const float* __restrict__ Dp,
                                  float* __restrict__ yg) {
    int b = blockIdx.x >> 5;
    int dbase = (blockIdx.x & 31) << 4;
    int n = threadIdx.x & 15;
    int d = dbase + (threadIdx.x >> 4);
    const int S = TT * RXW;

    float Ac = -__expf(A_log[d * DS + n]);
    float wtn = dtw[d * DTR + n];
    float dbv = dtb[d];
    float Dv = Dp[d];
    float h = 0.f;
    int tbase = b << 9;
#pragma unroll 2
    for (int l = 0; l < LL; l++) {
        int t = tbase + l;
        const float* p = xp + (size_t)t * RXW;
        float dtn = p[n] + p[S + n] + p[2*S + n] + p[3*S + n];
        float Bn  = p[16+n] + p[S+16+n] + p[2*S+16+n] + p[3*S+16+n];
        float Cn  = p[32+n] + p[S+32+n] + p[2*S+32+n] + p[3*S+32+n];
        float term = dtn * wtn;
#pragma unroll
        for (int o = 8; o > 0; o >>= 1)
            term += __shfl_xor_sync(0xffffffffu, term, o, 16);
        float sp = term + dbv;
        float del = (sp > 20.f) ? sp : log1pf(__expf(sp));
        float uu = u[(size_t)t * DI + d];
        h = fmaf(__expf(del * Ac), h, del * uu * Bn);
        float yp = h * Cn;
#pragma unroll
        for (int o = 8; o > 0; o >>= 1)
            yp += __shfl_xor_sync(0xffffffffu, yp, o, 16);
        if (n == 0) {
            float z = xz[(size_t)t * XZW + DI + d];
            float sz = z / (1.f + __expf(-z));
            yg[(size_t)t * DI + d] = (yp + uu * Dv) * sz;
        }
    }
}

// ---------------------------------------------------------------------------
// Host launcher
// ---------------------------------------------------------------------------
extern "C" void kernel_launch(void* const* d_in, const int* in_sizes, int n_in,
                              void* d_out, int out_size) {
    const float* x      = (const float*)d_in[0];
    const float* norm_w = (const float*)d_in[1];
    const float* W_in   = (const float*)d_in[2];
    const float* b_in   = (const float*)d_in[3];
    const float* conv_w = (const float*)d_in[4];
    const float* W_x    = (const float*)d_in[5];
    const float* dt_w   = (const float*)d_in[6];
    const float* dt_b   = (const float*)d_in[7];
    const float* A_log  = (const float*)d_in[8];
    const float* Dp     = (const float*)d_in[9];
    const float* W_out  = (const float*)d_in[10];
    const float* b_out  = (const float*)d_in[11];
    float* xcur = (float*)d_out;

    float *scale, *xz, *u, *xdbc, *yg;
    cudaGetSymbolAddress((void**)&scale, g_scale);
    cudaGetSymbolAddress((void**)&xz, g_xz);
    cudaGetSymbolAddress((void**)&u, g_u);
    cudaGetSymbolAddress((void**)&xdbc, g_xdbc);
    cudaGetSymbolAddress((void**)&yg, g_yg);

    cudaMemcpyAsync(xcur, x, (size_t)TT * DM * sizeof(float),
                    cudaMemcpyDeviceToDevice);

    const int ew_blocks = (TT * DI) / 256;  // 4096

    for (int i = 0; i < NL; i++) {
        // rmsnorm scale per token (applied inside in-proj A-loader)
        rms_scale_kernel<<<TT / 8, 256>>>(xcur, scale);

        // in-proj: xz[2048,1024] = rmsnorm(x) @ W_in^T + b_in
        gemm_tn_kernel<<<dim3(XZW / 64, TT / 128, 1), 256>>>(
            xcur, W_in + (size_t)i * XZW * DM, b_in + (size_t)i * XZW,
            scale, norm_w + (size_t)i * DM,
            xz, TT, XZW, DM, DM, /*mode=*/0);

        conv_silu_kernel<<<ew_blocks, 256>>>(xz, conv_w + (size_t)i * DI * DC, u);

        // x-proj: xdbc partials[4][2048,48] = u @ W_x^T (split-K, summed in scan)
        gemm_tn_kernel<<<dim3(1, TT / 128, XSPLIT), 256>>>(
            u, W_x + (size_t)i * RXW * DI, nullptr, nullptr, nullptr,
            xdbc, TT, RXW, DI, DI / XSPLIT, /*mode=*/1);

        // fused: delta-proj + softplus + scan + gate
        scan_fused_kernel<<<BB * (DI / 16), 256>>>(
            xdbc, u, xz, A_log + (size_t)i * DI * DS,
            dt_w + (size_t)i * DI * DTR, dt_b + (size_t)i * DI,
            Dp + (size_t)i * DI, yg);

        // out-proj + residual: xcur += yg @ W_out^T + b_out (split-K2, atomic)
        gemm_tn_kernel<<<dim3(DM / 64, TT / 128, 2), 256>>>(
            yg, W_out + (size_t)i * DM * DI, b_out + (size_t)i * DM,
            nullptr, nullptr,
            xcur, TT, DM, DI, DI / 2, /*mode=*/2);
    }
}

// round 13
// speedup vs baseline: 2.2655x; 2.2655x over previous
#include <cuda_runtime.h>
#include <cuda_bf16.h>
#include <cstdint>
#include <math.h>

// Problem constants
#define BB 4
#define LL 512
#define DM 256
#define NL 6
#define DI 512
#define DS 16
#define DC 4
#define DTR 16
#define TT (BB * LL)        // 2048 tokens
#define XZW (2 * DI)        // 1024
#define RXW (DTR + 2 * DS)  // 48
#define XSPLIT 4            // split-K factor for x-proj

// ---------------------------------------------------------------------------
// Scratch (device globals; no allocation allowed)
// ---------------------------------------------------------------------------
__device__ __align__(16) float g_scale[TT];
__device__ __align__(16) float g_xz[TT * XZW];
__device__ __align__(16) float g_u[TT * DI];
__device__ __align__(16) float g_zs[TT * DI];               // silu(z)
__device__ __align__(16) float g_xdbc_p[XSPLIT * TT * RXW]; // K-split partials
__device__ __align__(16) float g_xdbc[TT * RXW];            // reduced
__device__ __align__(16) float g_delta[TT * DI];
__device__ __align__(16) float g_du[TT * DI];               // delta*u
__device__ __align__(16) float g_gd[TT * DI];               // u*D
__device__ __align__(16) float g_yg[TT * DI];

// ---------------------------------------------------------------------------
// RMSNorm scale: scale[t] = rsqrt(mean(x[t]^2)+eps). One warp per token.
// ---------------------------------------------------------------------------
__global__ void rms_scale_kernel(const float* __restrict__ x,
                                 float* __restrict__ scale) {
    int w = (blockIdx.x * blockDim.x + threadIdx.x) >> 5;
    int lane = threadIdx.x & 31;
    const float* xp = x + (size_t)w * DM + lane * 8;
    float4 a = *(const float4*)xp;
    float4 b = *(const float4*)(xp + 4);
    float sq = a.x*a.x + a.y*a.y + a.z*a.z + a.w*a.w
             + b.x*b.x + b.y*b.y + b.z*b.z + b.w*b.w;
#pragma unroll
    for (int o = 16; o > 0; o >>= 1) sq += __shfl_xor_sync(0xffffffffu, sq, o);
    if (lane == 0) scale[w] = rsqrtf(sq / (float)DM + 1e-5f);
}

// ---------------------------------------------------------------------------
// SIMT TN GEMM, double-buffered, 128x64 tile, 8x4 per thread, BK=16.
// mode 0: direct store (+bias)
// mode 1: store to C + z*M*N (per-split partial output)
// mode 2: atomicAdd into C (+bias only from split z==0)
// ---------------------------------------------------------------------------
__global__ void __launch_bounds__(256, 2)
gemm_tn_kernel(const float* __restrict__ A, const float* __restrict__ Bw,
               const float* __restrict__ bias,
               const float* __restrict__ arow, const float* __restrict__ acol,
               float* __restrict__ C, int M, int N, int K,
               int kchunk, int mode) {
    __shared__ float As[2][16][132];
    __shared__ float Bs[2][16][68];
    int tid = threadIdx.x;
    int m0 = blockIdx.y * 128;
    int n0 = blockIdx.x * 64;
    int kbeg = blockIdx.z * kchunk;
    int kend = kbeg + kchunk;
    int nt = N - n0; if (nt > 64) nt = 64;

    int lrow = tid >> 1;
    int lcol = (tid & 1) * 8;
    int brow = tid >> 2;
    int bcol = (tid & 3) * 4;
    float rs = arow ? arow[m0 + lrow] : 1.f;
    const float* ap = A + (size_t)(m0 + lrow) * K + lcol;
    const float* bp = Bw + (size_t)(n0 + brow) * K + bcol;
    bool bvalid = brow < nt;

    int tx = tid & 15;
    int ty = tid >> 4;

    float acc[8][4];
#pragma unroll
    for (int i = 0; i < 8; i++)
#pragma unroll
        for (int j = 0; j < 4; j++) acc[i][j] = 0.f;

    float4 sa0, sa1, sb0;
    {
        sa0 = *(const float4*)(ap + kbeg);
        sa1 = *(const float4*)(ap + kbeg + 4);
        if (acol) {
            float4 w0 = *(const float4*)(acol + kbeg + lcol);
            float4 w1 = *(const float4*)(acol + kbeg + lcol + 4);
            sa0.x *= w0.x; sa0.y *= w0.y; sa0.z *= w0.z; sa0.w *= w0.w;
            sa1.x *= w1.x; sa1.y *= w1.y; sa1.z *= w1.z; sa1.w *= w1.w;
        }
        sa0.x *= rs; sa0.y *= rs; sa0.z *= rs; sa0.w *= rs;
        sa1.x *= rs; sa1.y *= rs; sa1.z *= rs; sa1.w *= rs;
        sb0 = bvalid ? *(const float4*)(bp + kbeg) : make_float4(0.f,0.f,0.f,0.f);
    }
    int buf = 0;
    As[0][lcol+0][lrow]=sa0.x; As[0][lcol+1][lrow]=sa0.y;
    As[0][lcol+2][lrow]=sa0.z; As[0][lcol+3][lrow]=sa0.w;
    As[0][lcol+4][lrow]=sa1.x; As[0][lcol+5][lrow]=sa1.y;
    As[0][lcol+6][lrow]=sa1.z; As[0][lcol+7][lrow]=sa1.w;
    Bs[0][bcol+0][brow]=sb0.x; Bs[0][bcol+1][brow]=sb0.y;
    Bs[0][bcol+2][brow]=sb0.z; Bs[0][bcol+3][brow]=sb0.w;
    __syncthreads();

    for (int k0 = kbeg; k0 < kend; k0 += 16) {
        bool more = (k0 + 16) < kend;
        if (more) {
            int kn = k0 + 16;
            sa0 = *(const float4*)(ap + kn);
            sa1 = *(const float4*)(ap + kn + 4);
            if (acol) {
                float4 w0 = *(const float4*)(acol + kn + lcol);
                float4 w1 = *(const float4*)(acol + kn + lcol + 4);
                sa0.x *= w0.x; sa0.y *= w0.y; sa0.z *= w0.z; sa0.w *= w0.w;
                sa1.x *= w1.x; sa1.y *= w1.y; sa1.z *= w1.z; sa1.w *= w1.w;
            }
            sa0.x *= rs; sa0.y *= rs; sa0.z *= rs; sa0.w *= rs;
            sa1.x *= rs; sa1.y *= rs; sa1.z *= rs; sa1.w *= rs;
            sb0 = bvalid ? *(const float4*)(bp + kn) : make_float4(0.f,0.f,0.f,0.f);
        }
#pragma unroll
        for (int kk = 0; kk < 16; kk++) {
            float4 a0 = *(float4*)&As[buf][kk][ty * 8];
            float4 a1 = *(float4*)&As[buf][kk][ty * 8 + 4];
            float4 b0 = *(float4*)&Bs[buf][kk][tx * 4];
            float a[8] = {a0.x,a0.y,a0.z,a0.w,a1.x,a1.y,a1.z,a1.w};
            float b[4] = {b0.x,b0.y,b0.z,b0.w};
#pragma unroll
            for (int i = 0; i < 8; i++)
#pragma unroll
                for (int j = 0; j < 4; j++)
                    acc[i][j] = fmaf(a[i], b[j], acc[i][j]);
        }
        if (more) {
            buf ^= 1;
            As[buf][lcol+0][lrow]=sa0.x; As[buf][lcol+1][lrow]=sa0.y;
            As[buf][lcol+2][lrow]=sa0.z; As[buf][lcol+3][lrow]=sa0.w;
            As[buf][lcol+4][lrow]=sa1.x; As[buf][lcol+5][lrow]=sa1.y;
            As[buf][lcol+6][lrow]=sa1.z; As[buf][lcol+7][lrow]=sa1.w;
            Bs[buf][bcol+0][brow]=sb0.x; Bs[buf][bcol+1][brow]=sb0.y;
            Bs[buf][bcol+2][brow]=sb0.z; Bs[buf][bcol+3][brow]=sb0.w;
            __syncthreads();
        }
    }

    if (mode == 2) {
        const float* bb = (blockIdx.z == 0) ? bias : nullptr;
#pragma unroll
        for (int i = 0; i < 8; i++) {
            int gm = m0 + ty * 8 + i;
#pragma unroll
            for (int j = 0; j < 4; j++) {
                int gn = n0 + tx * 4 + j;
                if (gn - n0 >= nt) continue;
                float v = acc[i][j];
                if (bb) v += bb[gn];
                atomicAdd(&C[(size_t)gm * N + gn], v);
            }
        }
    } else {
        float* Cp = C + (mode == 1 ? (size_t)blockIdx.z * M * N : 0);
        int colb = tx * 4;
        if (colb < nt) {
            float4 bv = make_float4(0.f,0.f,0.f,0.f);
            if (bias) bv = *(const float4*)(bias + n0 + colb);
#pragma unroll
            for (int i = 0; i < 8; i++) {
                int gm = m0 + ty * 8 + i;
                float4 v = make_float4(acc[i][0]+bv.x, acc[i][1]+bv.y,
                                       acc[i][2]+bv.z, acc[i][3]+bv.w);
                *(float4*)(Cp + (size_t)gm * N + n0 + colb) = v;
            }
        }
    }
}

// ---------------------------------------------------------------------------
// Causal depthwise conv (width 4) + SiLU -> u; also zs = silu(z).
// ---------------------------------------------------------------------------
__global__ void conv_silu_kernel(const float* __restrict__ xz,
                                 const float* __restrict__ cw,
                                 float* __restrict__ u,
                                 float* __restrict__ zs) {
    int idx = blockIdx.x * blockDim.x + threadIdx.x;
    int t = idx >> 9;
    int d = idx & 511;
    int l = t & 511;
    float acc = 0.f;
#pragma unroll
    for (int j = 0; j < 4; j++) {
        int ll = l - 3 + j;
        if (ll >= 0) acc = fmaf(cw[d * 4 + j], xz[(size_t)(t - 3 + j) * XZW + d], acc);
    }
    u[idx] = acc / (1.f + __expf(-acc));
    float z = xz[(size_t)t * XZW + DI + d];
    zs[idx] = z / (1.f + __expf(-z));
}

// ---------------------------------------------------------------------------
// Reduce split-K x-proj partials: xdbc = sum_z xdbc_p[z]
// ---------------------------------------------------------------------------
__global__ void xreduce_kernel(const float* __restrict__ xp,
                               float* __restrict__ xo) {
    int idx = blockIdx.x * blockDim.x + threadIdx.x;
    const int S = TT * RXW;
    float v = xp[idx] + xp[S + idx] + xp[2*S + idx] + xp[3*S + idx];
    xo[idx] = v;
}

// ---------------------------------------------------------------------------
// delta = softplus(dt @ dt_w^T + dt_b); du = delta*u; gd = u*D
// ---------------------------------------------------------------------------
__global__ void delta_kernel(const float* __restrict__ xdbc,
                             const float* __restrict__ dtw,
                             const float* __restrict__ dtb,
                             const float* __restrict__ u,
                             const float* __restrict__ Dp,
                             float* __restrict__ delta,
                             float* __restrict__ du,
                             float* __restrict__ gd) {
    int idx = blockIdx.x * blockDim.x + threadIdx.x;
    int t = idx >> 9;
    int d = idx & 511;
    float s = dtb[d];
#pragma unroll
    for (int r = 0; r < DTR; r++) s = fmaf(xdbc[t * RXW + r], dtw[d * DTR + r], s);
    float del = (s > 20.f) ? s : log1pf(__expf(s));
    float uu = u[idx];
    delta[idx] = del;
    du[idx] = del * uu;
    gd[idx] = uu * Dp[d];
}

// ---------------------------------------------------------------------------
// Selective scan, depth-2 software pipeline; gate at n==0 writer.
// Thread = (b, d, n). 16-lane groups share d.
// ---------------------------------------------------------------------------
__global__ void scan_kernel(const float* __restrict__ delta,
                            const float* __restrict__ du,
                            const float* __restrict__ xdbc,
                            const float* __restrict__ A_log,
                            const float* __restrict__ zs,
                            const float* __restrict__ gd,
                            float* __restrict__ yg) {
    int b = blockIdx.x >> 5;
    int dbase = (blockIdx.x & 31) << 4;
    int n = threadIdx.x & 15;
    int d = dbase + (threadIdx.x >> 4);
    int tbase = b << 9;

    float Ac = -__expf(A_log[d * DS + n]);
    float h = 0.f;

    const float* pd = delta + (size_t)tbase * DI + d;
    const float* pu = du + (size_t)tbase * DI + d;
    const float* px = xdbc + (size_t)tbase * RXW;
    const float* pz = zs + (size_t)tbase * DI + d;
    const float* pg = gd + (size_t)tbase * DI + d;
    float* py = yg + (size_t)tbase * DI + d;

    // depth-2 pipeline registers
    float fdel[2], fdu[2], fB[2], fC[2];
    fdel[0] = pd[0];  fdu[0] = pu[0];
    fB[0] = px[16 + n];        fC[0] = px[32 + n];
    fdel[1] = pd[DI]; fdu[1] = pu[DI];
    fB[1] = px[RXW + 16 + n];  fC[1] = px[RXW + 32 + n];

#pragma unroll 4
    for (int l = 0; l < LL; l++) {
        int s = l & 1;
        float del = fdel[s], duu = fdu[s], Bn = fB[s], Cn = fC[s];
        int lp = l + 2;
        if (lp < LL) {   // prefetch t+2 (independent of compute chain)
            fdel[s] = pd[(size_t)lp * DI];
            fdu[s]  = pu[(size_t)lp * DI];
            fB[s]   = px[lp * RXW + 16 + n];
            fC[s]   = px[lp * RXW + 32 + n];
        }
        float a = __expf(del * Ac);
        h = fmaf(a, h, duu * Bn);
        float yp = h * Cn;
#pragma unroll
        for (int o = 8; o > 0; o >>= 1)
            yp += __shfl_xor_sync(0xffffffffu, yp, o, 16);
        if (n == 0)
            py[(size_t)l * DI] = (yp + pg[(size_t)l * DI]) * pz[(size_t)l * DI];
    }
}

// ---------------------------------------------------------------------------
// Host launcher
// ---------------------------------------------------------------------------
extern "C" void kernel_launch(void* const* d_in, const int* in_sizes, int n_in,
                              void* d_out, int out_size) {
    const float* x      = (const float*)d_in[0];
    const float* norm_w = (const float*)d_in[1];
    const float* W_in   = (const float*)d_in[2];
    const float* b_in   = (const float*)d_in[3];
    const float* conv_w = (const float*)d_in[4];
    const float* W_x    = (const float*)d_in[5];
    const float* dt_w   = (const float*)d_in[6];
    const float* dt_b   = (const float*)d_in[7];
    const float* A_log  = (const float*)d_in[8];
    const float* Dp     = (const float*)d_in[9];
    const float* W_out  = (const float*)d_in[10];
    const float* b_out  = (const float*)d_in[11];
    float* xcur = (float*)d_out;

    float *scale, *xz, *u, *zs, *xdbc_p, *xdbc, *delta, *du, *gd, *yg;
    cudaGetSymbolAddress((void**)&scale, g_scale);
    cudaGetSymbolAddress((void**)&xz, g_xz);
    cudaGetSymbolAddress((void**)&u, g_u);
    cudaGetSymbolAddress((void**)&zs, g_zs);
    cudaGetSymbolAddress((void**)&xdbc_p, g_xdbc_p);
    cudaGetSymbolAddress((void**)&xdbc, g_xdbc);
    cudaGetSymbolAddress((void**)&delta, g_delta);
    cudaGetSymbolAddress((void**)&du, g_du);
    cudaGetSymbolAddress((void**)&gd, g_gd);
    cudaGetSymbolAddress((void**)&yg, g_yg);

    cudaMemcpyAsync(xcur, x, (size_t)TT * DM * sizeof(float),
                    cudaMemcpyDeviceToDevice);

    const int ew_blocks = (TT * DI) / 256;      // 4096
    const int xr_blocks = (TT * RXW) / 256;     // 384

    for (int i = 0; i < NL; i++) {
        rms_scale_kernel<<<TT / 8, 256>>>(xcur, scale);

        gemm_tn_kernel<<<dim3(XZW / 64, TT / 128, 1), 256>>>(
            xcur, W_in + (size_t)i * XZW * DM, b_in + (size_t)i * XZW,
            scale, norm_w + (size_t)i * DM,
            xz, TT, XZW, DM, DM, /*mode=*/0);

        conv_silu_kernel<<<ew_blocks, 256>>>(xz, conv_w + (size_t)i * DI * DC,
                                             u, zs);

        gemm_tn_kernel<<<dim3(1, TT / 128, XSPLIT), 256>>>(
            u, W_x + (size_t)i * RXW * DI, nullptr, nullptr, nullptr,
            xdbc_p, TT, RXW, DI, DI / XSPLIT, /*mode=*/1);

        xreduce_kernel<<<xr_blocks, 256>>>(xdbc_p, xdbc);

        delta_kernel<<<ew_blocks, 256>>>(xdbc, dt_w + (size_t)i * DI * DTR,
                                         dt_b + (size_t)i * DI, u,
                                         Dp + (size_t)i * DI,
                                         delta, du, gd);

        scan_kernel<<<BB * (DI / 16), 256>>>(delta, du, xdbc,
                                             A_log + (size_t)i * DI * DS,
                                             zs, gd, yg);

        gemm_tn_kernel<<<dim3(DM / 64, TT / 128, 2), 256>>>(
            yg, W_out + (size_t)i * DM * DI, b_out + (size_t)i * DM,
            nullptr, nullptr,
            xcur, TT, DM, DI, DI / 2, /*mode=*/2);
    }
}

// round 14
// speedup vs baseline: 3.3777x; 1.4910x over previous
#include <cuda_runtime.h>
#include <cuda_bf16.h>
#include <cstdint>
#include <math.h>

// Problem constants
#define BB 4
#define LL 512
#define DM 256
#define NL 6
#define DI 512
#define DS 16
#define DC 4
#define DTR 16
#define TT (BB * LL)        // 2048 tokens
#define XZW (2 * DI)        // 1024
#define RXW (DTR + 2 * DS)  // 48
#define XSPLIT 4            // split-K factor for x-proj
#define NCH 8               // scan chunks over L
#define CHL (LL / NCH)      // 64 steps per chunk
#define CARRY (BB * DI * DS)  // 32768 carries per chunk

// ---------------------------------------------------------------------------
// Scratch (device globals; no allocation allowed)
// ---------------------------------------------------------------------------
__device__ __align__(16) float g_scale[TT];
__device__ __align__(16) float g_xz[TT * XZW];
__device__ __align__(16) float g_u[TT * DI];
__device__ __align__(16) float g_xdbc_p[XSPLIT * TT * RXW]; // K-split partials
__device__ __align__(16) float g_xdbc[TT * RXW];            // reduced
__device__ __align__(16) float g_delta[TT * DI];
__device__ __align__(16) float g_ap[NCH * CARRY];           // chunk prod(a)
__device__ __align__(16) float g_he[NCH * CARRY];           // chunk h_end
__device__ __align__(16) float g_yg[TT * DI];

// ---------------------------------------------------------------------------
// RMSNorm scale: scale[t] = rsqrt(mean(x[t]^2)+eps). One warp per token.
// ---------------------------------------------------------------------------
__global__ void rms_scale_kernel(const float* __restrict__ x,
                                 float* __restrict__ scale) {
    int w = (blockIdx.x * blockDim.x + threadIdx.x) >> 5;
    int lane = threadIdx.x & 31;
    const float* xp = x + (size_t)w * DM + lane * 8;
    float4 a = *(const float4*)xp;
    float4 b = *(const float4*)(xp + 4);
    float sq = a.x*a.x + a.y*a.y + a.z*a.z + a.w*a.w
             + b.x*b.x + b.y*b.y + b.z*b.z + b.w*b.w;
#pragma unroll
    for (int o = 16; o > 0; o >>= 1) sq += __shfl_xor_sync(0xffffffffu, sq, o);
    if (lane == 0) scale[w] = rsqrtf(sq / (float)DM + 1e-5f);
}

// ---------------------------------------------------------------------------
// SIMT TN GEMM, double-buffered, 128x64 tile, 8x4 per thread, BK=16.
// mode 0: direct store (+bias)
// mode 1: store to C + z*M*N (per-split partial output)
// mode 2: atomicAdd into C (+bias only from split z==0)
// ---------------------------------------------------------------------------
__global__ void __launch_bounds__(256, 2)
gemm_tn_kernel(const float* __restrict__ A, const float* __restrict__ Bw,
               const float* __restrict__ bias,
               const float* __restrict__ arow, const float* __restrict__ acol,
               float* __restrict__ C, int M, int N, int K,
               int kchunk, int mode) {
    __shared__ float As[2][16][132];
    __shared__ float Bs[2][16][68];
    int tid = threadIdx.x;
    int m0 = blockIdx.y * 128;
    int n0 = blockIdx.x * 64;
    int kbeg = blockIdx.z * kchunk;
    int kend = kbeg + kchunk;
    int nt = N - n0; if (nt > 64) nt = 64;

    int lrow = tid >> 1;
    int lcol = (tid & 1) * 8;
    int brow = tid >> 2;
    int bcol = (tid & 3) * 4;
    float rs = arow ? arow[m0 + lrow] : 1.f;
    const float* ap = A + (size_t)(m0 + lrow) * K + lcol;
    const float* bp = Bw + (size_t)(n0 + brow) * K + bcol;
    bool bvalid = brow < nt;

    int tx = tid & 15;
    int ty = tid >> 4;

    float acc[8][4];
#pragma unroll
    for (int i = 0; i < 8; i++)
#pragma unroll
        for (int j = 0; j < 4; j++) acc[i][j] = 0.f;

    float4 sa0, sa1, sb0;
    {
        sa0 = *(const float4*)(ap + kbeg);
        sa1 = *(const float4*)(ap + kbeg + 4);
        if (acol) {
            float4 w0 = *(const float4*)(acol + kbeg + lcol);
            float4 w1 = *(const float4*)(acol + kbeg + lcol + 4);
            sa0.x *= w0.x; sa0.y *= w0.y; sa0.z *= w0.z; sa0.w *= w0.w;
            sa1.x *= w1.x; sa1.y *= w1.y; sa1.z *= w1.z; sa1.w *= w1.w;
        }
        sa0.x *= rs; sa0.y *= rs; sa0.z *= rs; sa0.w *= rs;
        sa1.x *= rs; sa1.y *= rs; sa1.z *= rs; sa1.w *= rs;
        sb0 = bvalid ? *(const float4*)(bp + kbeg) : make_float4(0.f,0.f,0.f,0.f);
    }
    int buf = 0;
    As[0][lcol+0][lrow]=sa0.x; As[0][lcol+1][lrow]=sa0.y;
    As[0][lcol+2][lrow]=sa0.z; As[0][lcol+3][lrow]=sa0.w;
    As[0][lcol+4][lrow]=sa1.x; As[0][lcol+5][lrow]=sa1.y;
    As[0][lcol+6][lrow]=sa1.z; As[0][lcol+7][lrow]=sa1.w;
    Bs[0][bcol+0][brow]=sb0.x; Bs[0][bcol+1][brow]=sb0.y;
    Bs[0][bcol+2][brow]=sb0.z; Bs[0][bcol+3][brow]=sb0.w;
    __syncthreads();

    for (int k0 = kbeg; k0 < kend; k0 += 16) {
        bool more = (k0 + 16) < kend;
        if (more) {
            int kn = k0 + 16;
            sa0 = *(const float4*)(ap + kn);
            sa1 = *(const float4*)(ap + kn + 4);
            if (acol) {
                float4 w0 = *(const float4*)(acol + kn + lcol);
                float4 w1 = *(const float4*)(acol + kn + lcol + 4);
                sa0.x *= w0.x; sa0.y *= w0.y; sa0.z *= w0.z; sa0.w *= w0.w;
                sa1.x *= w1.x; sa1.y *= w1.y; sa1.z *= w1.z; sa1.w *= w1.w;
            }
            sa0.x *= rs; sa0.y *= rs; sa0.z *= rs; sa0.w *= rs;
            sa1.x *= rs; sa1.y *= rs; sa1.z *= rs; sa1.w *= rs;
            sb0 = bvalid ? *(const float4*)(bp + kn) : make_float4(0.f,0.f,0.f,0.f);
        }
#pragma unroll
        for (int kk = 0; kk < 16; kk++) {
            float4 a0 = *(float4*)&As[buf][kk][ty * 8];
            float4 a1 = *(float4*)&As[buf][kk][ty * 8 + 4];
            float4 b0 = *(float4*)&Bs[buf][kk][tx * 4];
            float a[8] = {a0.x,a0.y,a0.z,a0.w,a1.x,a1.y,a1.z,a1.w};
            float b[4] = {b0.x,b0.y,b0.z,b0.w};
#pragma unroll
            for (int i = 0; i < 8; i++)
#pragma unroll
                for (int j = 0; j < 4; j++)
                    acc[i][j] = fmaf(a[i], b[j], acc[i][j]);
        }
        if (more) {
            buf ^= 1;
            As[buf][lcol+0][lrow]=sa0.x; As[buf][lcol+1][lrow]=sa0.y;
            As[buf][lcol+2][lrow]=sa0.z; As[buf][lcol+3][lrow]=sa0.w;
            As[buf][lcol+4][lrow]=sa1.x; As[buf][lcol+5][lrow]=sa1.y;
            As[buf][lcol+6][lrow]=sa1.z; As[buf][lcol+7][lrow]=sa1.w;
            Bs[buf][bcol+0][brow]=sb0.x; Bs[buf][bcol+1][brow]=sb0.y;
            Bs[buf][bcol+2][brow]=sb0.z; Bs[buf][bcol+3][brow]=sb0.w;
            __syncthreads();
        }
    }

    if (mode == 2) {
        const float* bb = (blockIdx.z == 0) ? bias : nullptr;
#pragma unroll
        for (int i = 0; i < 8; i++) {
            int gm = m0 + ty * 8 + i;
#pragma unroll
            for (int j = 0; j < 4; j++) {
                int gn = n0 + tx * 4 + j;
                if (gn - n0 >= nt) continue;
                float v = acc[i][j];
                if (bb) v += bb[gn];
                atomicAdd(&C[(size_t)gm * N + gn], v);
            }
        }
    } else {
        float* Cp = C + (mode == 1 ? (size_t)blockIdx.z * M * N : 0);
        int colb = tx * 4;
        if (colb < nt) {
            float4 bv = make_float4(0.f,0.f,0.f,0.f);
            if (bias) bv = *(const float4*)(bias + n0 + colb);
#pragma unroll
            for (int i = 0; i < 8; i++) {
                int gm = m0 + ty * 8 + i;
                float4 v = make_float4(acc[i][0]+bv.x, acc[i][1]+bv.y,
                                       acc[i][2]+bv.z, acc[i][3]+bv.w);
                *(float4*)(Cp + (size_t)gm * N + n0 + colb) = v;
            }
        }
    }
}

// ---------------------------------------------------------------------------
// Causal depthwise conv (width 4) + SiLU -> u
// ---------------------------------------------------------------------------
__global__ void conv_silu_kernel(const float* __restrict__ xz,
                                 const float* __restrict__ cw,
                                 float* __restrict__ u) {
    int idx = blockIdx.x * blockDim.x + threadIdx.x;
    int t = idx >> 9;
    int d = idx & 511;
    int l = t & 511;
    float acc = 0.f;
#pragma unroll
    for (int j = 0; j < 4; j++) {
        int ll = l - 3 + j;
        if (ll >= 0) acc = fmaf(cw[d * 4 + j], xz[(size_t)(t - 3 + j) * XZW + d], acc);
    }
    u[idx] = acc / (1.f + __expf(-acc));
}

// ---------------------------------------------------------------------------
// Reduce split-K x-proj partials: xdbc = sum_z xdbc_p[z]
// ---------------------------------------------------------------------------
__global__ void xreduce_kernel(const float* __restrict__ xp,
                               float* __restrict__ xo) {
    int idx = blockIdx.x * blockDim.x + threadIdx.x;
    const int S = TT * RXW;
    xo[idx] = xp[idx] + xp[S + idx] + xp[2*S + idx] + xp[3*S + idx];
}

// ---------------------------------------------------------------------------
// delta = softplus(dt @ dt_w^T + dt_b)
// ---------------------------------------------------------------------------
__global__ void delta_kernel(const float* __restrict__ xdbc,
                             const float* __restrict__ dtw,
                             const float* __restrict__ dtb,
                             float* __restrict__ delta) {
    int idx = blockIdx.x * blockDim.x + threadIdx.x;
    int t = idx >> 9;
    int d = idx & 511;
    float s = dtb[d];
#pragma unroll
    for (int r = 0; r < DTR; r++) s = fmaf(xdbc[t * RXW + r], dtw[d * DTR + r], s);
    delta[idx] = (s > 20.f) ? s : log1pf(__expf(s));
}

// ---------------------------------------------------------------------------
// Chunked scan pass A: per (b,d,n,chunk) compute prod(a) and h_end from 0.
// grid = BB*32*NCH blocks (1024), 256 threads; thread = (drel, n).
// blockIdx.x = ((b*32 + dg)*NCH + c)
// ---------------------------------------------------------------------------
__global__ void scanA_kernel(const float* __restrict__ delta,
                             const float* __restrict__ u,
                             const float* __restrict__ xdbc,
                             const float* __restrict__ A_log,
                             float* __restrict__ ap_out,
                             float* __restrict__ he_out) {
    int bi = blockIdx.x;
    int c = bi & (NCH - 1);
    int dg = (bi >> 3) & 31;
    int b = bi >> 8;
    int n = threadIdx.x & 15;
    int d = (dg << 4) + (threadIdx.x >> 4);
    int tbase = (b << 9) + c * CHL;

    float Ac = -__expf(A_log[d * DS + n]);
    const float* pd = delta + (size_t)tbase * DI + d;
    const float* pu = u + (size_t)tbase * DI + d;
    const float* px = xdbc + (size_t)tbase * RXW + 16 + n;

    float h = 0.f, ap = 1.f;
#pragma unroll 4
    for (int l = 0; l < CHL; l++) {
        float del = pd[(size_t)l * DI];
        float uu = pu[(size_t)l * DI];
        float Bn = px[l * RXW];
        float a = __expf(del * Ac);
        h = fmaf(a, h, del * uu * Bn);
        ap *= a;
    }
    int idx = ((b * DI + d) << 4) + n;
    ap_out[c * CARRY + idx] = ap;
    he_out[c * CARRY + idx] = h;
}

// ---------------------------------------------------------------------------
// Chunked scan pass B: fold carries of preceding chunks, replay chunk with
// correct h0, reduce y over n, gate inline. Same grid as pass A.
// ---------------------------------------------------------------------------
__global__ void scanB_kernel(const float* __restrict__ delta,
                             const float* __restrict__ u,
                             const float* __restrict__ xdbc,
                             const float* __restrict__ A_log,
                             const float* __restrict__ xz,
                             const float* __restrict__ Dp,
                             const float* __restrict__ ap_in,
                             const float* __restrict__ he_in,
                             float* __restrict__ yg) {
    int bi = blockIdx.x;
    int c = bi & (NCH - 1);
    int dg = (bi >> 3) & 31;
    int b = bi >> 8;
    int n = threadIdx.x & 15;
    int d = (dg << 4) + (threadIdx.x >> 4);
    int tbase = (b << 9) + c * CHL;

    float Ac = -__expf(A_log[d * DS + n]);
    float Dv = Dp[d];

    // fold carries: h after chunks 0..c-1
    int idx = ((b * DI + d) << 4) + n;
    float h = 0.f;
    for (int j = 0; j < c; j++)
        h = fmaf(ap_in[j * CARRY + idx], h, he_in[j * CARRY + idx]);

    const float* pd = delta + (size_t)tbase * DI + d;
    const float* pu = u + (size_t)tbase * DI + d;
    const float* px = xdbc + (size_t)tbase * RXW;
    const float* pz = xz + (size_t)tbase * XZW + DI + d;
    float* py = yg + (size_t)tbase * DI + d;

#pragma unroll 4
    for (int l = 0; l < CHL; l++) {
        float del = pd[(size_t)l * DI];
        float uu = pu[(size_t)l * DI];
        float Bn = px[l * RXW + 16 + n];
        float Cn = px[l * RXW + 32 + n];
        float a = __expf(del * Ac);
        h = fmaf(a, h, del * uu * Bn);
        float yp = h * Cn;
#pragma unroll
        for (int o = 8; o > 0; o >>= 1)
            yp += __shfl_xor_sync(0xffffffffu, yp, o, 16);
        if (n == 0) {
            float z = pz[(size_t)l * XZW];
            float sz = z / (1.f + __expf(-z));
            py[(size_t)l * DI] = (yp + uu * Dv) * sz;
        }
    }
}

// ---------------------------------------------------------------------------
// Host launcher
// ---------------------------------------------------------------------------
extern "C" void kernel_launch(void* const* d_in, const int* in_sizes, int n_in,
                              void* d_out, int out_size) {
    const float* x      = (const float*)d_in[0];
    const float* norm_w = (const float*)d_in[1];
    const float* W_in   = (const float*)d_in[2];
    const float* b_in   = (const float*)d_in[3];
    const float* conv_w = (const float*)d_in[4];
    const float* W_x    = (const float*)d_in[5];
    const float* dt_w   = (const float*)d_in[6];
    const float* dt_b   = (const float*)d_in[7];
    const float* A_log  = (const float*)d_in[8];
    const float* Dp     = (const float*)d_in[9];
    const float* W_out  = (const float*)d_in[10];
    const float* b_out  = (const float*)d_in[11];
    float* xcur = (float*)d_out;

    float *scale, *xz, *u, *xdbc_p, *xdbc, *delta, *ap, *he, *yg;
    cudaGetSymbolAddress((void**)&scale, g_scale);
    cudaGetSymbolAddress((void**)&xz, g_xz);
    cudaGetSymbolAddress((void**)&u, g_u);
    cudaGetSymbolAddress((void**)&xdbc_p, g_xdbc_p);
    cudaGetSymbolAddress((void**)&xdbc, g_xdbc);
    cudaGetSymbolAddress((void**)&delta, g_delta);
    cudaGetSymbolAddress((void**)&ap, g_ap);
    cudaGetSymbolAddress((void**)&he, g_he);
    cudaGetSymbolAddress((void**)&yg, g_yg);

    cudaMemcpyAsync(xcur, x, (size_t)TT * DM * sizeof(float),
                    cudaMemcpyDeviceToDevice);

    const int ew_blocks = (TT * DI) / 256;      // 4096
    const int xr_blocks = (TT * RXW) / 256;     // 384
    const int sc_blocks = BB * 32 * NCH;        // 1024

    for (int i = 0; i < NL; i++) {
        rms_scale_kernel<<<TT / 8, 256>>>(xcur, scale);

        gemm_tn_kernel<<<dim3(XZW / 64, TT / 128, 1), 256>>>(
            xcur, W_in + (size_t)i * XZW * DM, b_in + (size_t)i * XZW,
            scale, norm_w + (size_t)i * DM,
            xz, TT, XZW, DM, DM, /*mode=*/0);

        conv_silu_kernel<<<ew_blocks, 256>>>(xz, conv_w + (size_t)i * DI * DC, u);

        gemm_tn_kernel<<<dim3(1, TT / 128, XSPLIT), 256>>>(
            u, W_x + (size_t)i * RXW * DI, nullptr, nullptr, nullptr,
            xdbc_p, TT, RXW, DI, DI / XSPLIT, /*mode=*/1);

        xreduce_kernel<<<xr_blocks, 256>>>(xdbc_p, xdbc);

        delta_kernel<<<ew_blocks, 256>>>(xdbc, dt_w + (size_t)i * DI * DTR,
                                         dt_b + (size_t)i * DI, delta);

        scanA_kernel<<<sc_blocks, 256>>>(delta, u, xdbc,
                                         A_log + (size_t)i * DI * DS, ap, he);

        scanB_kernel<<<sc_blocks, 256>>>(delta, u, xdbc,
                                         A_log + (size_t)i * DI * DS,
                                         xz, Dp + (size_t)i * DI,
                                         ap, he, yg);

        gemm_tn_kernel<<<dim3(DM / 64, TT / 128, 2), 256>>>(
            yg, W_out + (size_t)i * DM * DI, b_out + (size_t)i * DM,
            nullptr, nullptr,
            xcur, TT, DM, DI, DI / 2, /*mode=*/2);
    }
}

// round 15
// speedup vs baseline: 3.5853x; 1.0615x over previous
#include <cuda_runtime.h>
#include <cuda_bf16.h>
#include <mma.h>
#include <cstdint>
#include <math.h>

using namespace nvcuda;

// Problem constants
#define BB 4
#define LL 512
#define DM 256
#define NL 6
#define DI 512
#define DS 16
#define DC 4
#define DTR 16
#define TT (BB * LL)        // 2048 tokens
#define XZW (2 * DI)        // 1024
#define RXW (DTR + 2 * DS)  // 48
#define XSPLIT 4            // split-K factor for x-proj
#define NCH 8               // scan chunks over L
#define CHL (LL / NCH)      // 64 steps per chunk
#define CARRY (BB * DI * DS)  // 32768 carries per chunk

// ---------------------------------------------------------------------------
// Scratch (device globals; no allocation allowed)
// ---------------------------------------------------------------------------
__device__ __align__(16) float g_scale[TT];
__device__ __align__(16) float g_xz[TT * XZW];
__device__ __align__(16) float g_u[TT * DI];
__device__ __align__(16) float g_xdbc_p[XSPLIT * TT * RXW]; // K-split partials
__device__ __align__(16) float g_xdbc[TT * RXW];            // reduced
__device__ __align__(16) float g_delta[TT * DI];
__device__ __align__(16) float g_ap[NCH * CARRY];           // chunk prod(a)
__device__ __align__(16) float g_he[NCH * CARRY];           // chunk h_end
__device__ __align__(16) float g_yg[TT * DI];

// ---------------------------------------------------------------------------
// RMSNorm scale: scale[t] = rsqrt(mean(x[t]^2)+eps). One warp per token.
// ---------------------------------------------------------------------------
__global__ void rms_scale_kernel(const float* __restrict__ x,
                                 float* __restrict__ scale) {
    int w = (blockIdx.x * blockDim.x + threadIdx.x) >> 5;
    int lane = threadIdx.x & 31;
    const float* xp = x + (size_t)w * DM + lane * 8;
    float4 a = *(const float4*)xp;
    float4 b = *(const float4*)(xp + 4);
    float sq = a.x*a.x + a.y*a.y + a.z*a.z + a.w*a.w
             + b.x*b.x + b.y*b.y + b.z*b.z + b.w*b.w;
#pragma unroll
    for (int o = 16; o > 0; o >>= 1) sq += __shfl_xor_sync(0xffffffffu, sq, o);
    if (lane == 0) scale[w] = rsqrtf(sq / (float)DM + 1e-5f);
}

// ---------------------------------------------------------------------------
// bf16-split TN GEMM on tensor cores (wmma), double-buffered smem pipeline.
// C[m,n] = sum_k (A[m,k]*arow[m]*acol[k]) * Bw[n,k]  (+bias[n]) (+addsrc)
// Tile 128x64, BK=32, 256 threads = 8 warps (4m x 2n), warp tile 32x32.
// Split: Ah*Bh + Ah*Bl + Al*Bh (error ~2^-16).
// mode 0: direct store (+bias); mode 1: store to C + z*M*N;
// mode 2: atomicAdd into C (+bias only from split z==0).
// ---------------------------------------------------------------------------
#define ASTR 40                      // bf16 elems per smem row (32 + 8 pad)
#define SM_AH 0
#define SM_AL (128 * ASTR * 2)               // 10240
#define SM_BH (SM_AL + 128 * ASTR * 2)       // 20480
#define SM_BL (SM_BH + 64 * ASTR * 2)        // 25600
#define SM_BUF (SM_BL + 64 * ASTR * 2)       // 30720 per buffer
#define SM_TOTAL (2 * SM_BUF)                // 61440
#define CSTR 68

__device__ __forceinline__ void hilo4(float4 v, uint2& hv, uint2& lv) {
    __nv_bfloat16 h0 = __float2bfloat16(v.x);
    __nv_bfloat16 h1 = __float2bfloat16(v.y);
    __nv_bfloat16 h2 = __float2bfloat16(v.z);
    __nv_bfloat16 h3 = __float2bfloat16(v.w);
    __nv_bfloat16 l0 = __float2bfloat16(v.x - __bfloat162float(h0));
    __nv_bfloat16 l1 = __float2bfloat16(v.y - __bfloat162float(h1));
    __nv_bfloat16 l2 = __float2bfloat16(v.z - __bfloat162float(h2));
    __nv_bfloat16 l3 = __float2bfloat16(v.w - __bfloat162float(h3));
    hv.x = (uint32_t)__bfloat16_as_ushort(h0) | ((uint32_t)__bfloat16_as_ushort(h1) << 16);
    hv.y = (uint32_t)__bfloat16_as_ushort(h2) | ((uint32_t)__bfloat16_as_ushort(h3) << 16);
    lv.x = (uint32_t)__bfloat16_as_ushort(l0) | ((uint32_t)__bfloat16_as_ushort(l1) << 16);
    lv.y = (uint32_t)__bfloat16_as_ushort(l2) | ((uint32_t)__bfloat16_as_ushort(l3) << 16);
}

__global__ void __launch_bounds__(256)
tc_gemm_kernel(const float* __restrict__ A, const float* __restrict__ Bw,
               const float* __restrict__ bias,
               const float* __restrict__ arow, const float* __restrict__ acol,
               float* __restrict__ C, int M, int N, int K,
               int kchunk, int mode) {
    extern __shared__ char smem[];
    int tid = threadIdx.x;
    int wid = tid >> 5;
    int m0 = blockIdx.y * 128;
    int n0 = blockIdx.x * 64;
    int kbeg = blockIdx.z * kchunk;
    int kend = kbeg + kchunk;
    int nt = N - n0; if (nt > 64) nt = 64;

    int wm = (wid & 3) * 32;
    int wn = (wid >> 2) * 32;

    wmma::fragment<wmma::accumulator, 16, 16, 16, float> acc[2][2];
#pragma unroll
    for (int i = 0; i < 2; i++)
#pragma unroll
        for (int j = 0; j < 2; j++) wmma::fill_fragment(acc[i][j], 0.f);

    // A loader: row tid>>1 (0..127), col half (tid&1)*16 -> 4 float4
    int a_row = tid >> 1;
    int a_cb = (tid & 1) * 16;
    float rs = arow ? arow[m0 + a_row] : 1.f;
    const float* ap = A + (size_t)(m0 + a_row) * K + a_cb;
    // B loader: row tid>>2 (0..63), col group (tid&3)*8 -> 2 float4
    int b_row = tid >> 2;
    int b_cb = (tid & 3) * 8;
    const float* bp = Bw + (size_t)(n0 + b_row) * K + b_cb;
    bool bvalid = b_row < nt;

    float4 va[4], vb[2];
    // prefetch chunk 0
#pragma unroll
    for (int q = 0; q < 4; q++) {
        float4 v = *(const float4*)(ap + kbeg + q * 4);
        if (acol) {
            float4 w = *(const float4*)(acol + kbeg + a_cb + q * 4);
            v.x *= w.x; v.y *= w.y; v.z *= w.z; v.w *= w.w;
        }
        v.x *= rs; v.y *= rs; v.z *= rs; v.w *= rs;
        va[q] = v;
    }
#pragma unroll
    for (int q = 0; q < 2; q++)
        vb[q] = bvalid ? *(const float4*)(bp + kbeg + q * 4)
                       : make_float4(0.f, 0.f, 0.f, 0.f);

    int buf = 0;
    // store chunk 0 into buf 0
    {
        __nv_bfloat16* ah = (__nv_bfloat16*)(smem + SM_AH);
        __nv_bfloat16* al = (__nv_bfloat16*)(smem + SM_AL);
        __nv_bfloat16* bh = (__nv_bfloat16*)(smem + SM_BH);
        __nv_bfloat16* bl = (__nv_bfloat16*)(smem + SM_BL);
#pragma unroll
        for (int q = 0; q < 4; q++) {
            uint2 hv, lv; hilo4(va[q], hv, lv);
            *(uint2*)&ah[a_row * ASTR + a_cb + q * 4] = hv;
            *(uint2*)&al[a_row * ASTR + a_cb + q * 4] = lv;
        }
#pragma unroll
        for (int q = 0; q < 2; q++) {
            uint2 hv, lv; hilo4(vb[q], hv, lv);
            *(uint2*)&bh[b_row * ASTR + b_cb + q * 4] = hv;
            *(uint2*)&bl[b_row * ASTR + b_cb + q * 4] = lv;
        }
    }
    __syncthreads();

    for (int k0 = kbeg; k0 < kend; k0 += 32) {
        bool more = (k0 + 32) < kend;
        if (more) {
            int kn = k0 + 32;
#pragma unroll
            for (int q = 0; q < 4; q++) {
                float4 v = *(const float4*)(ap + kn + q * 4);
                if (acol) {
                    float4 w = *(const float4*)(acol + kn + a_cb + q * 4);
                    v.x *= w.x; v.y *= w.y; v.z *= w.z; v.w *= w.w;
                }
                v.x *= rs; v.y *= rs; v.z *= rs; v.w *= rs;
                va[q] = v;
            }
#pragma unroll
            for (int q = 0; q < 2; q++)
                vb[q] = bvalid ? *(const float4*)(bp + kn + q * 4)
                               : make_float4(0.f, 0.f, 0.f, 0.f);
        }

        // MMA on current buffer
        {
            const __nv_bfloat16* ah = (const __nv_bfloat16*)(smem + buf * SM_BUF + SM_AH);
            const __nv_bfloat16* al = (const __nv_bfloat16*)(smem + buf * SM_BUF + SM_AL);
            const __nv_bfloat16* bh = (const __nv_bfloat16*)(smem + buf * SM_BUF + SM_BH);
            const __nv_bfloat16* bl = (const __nv_bfloat16*)(smem + buf * SM_BUF + SM_BL);
#pragma unroll
            for (int ks = 0; ks < 32; ks += 16) {
                wmma::fragment<wmma::matrix_a, 16, 16, 16, __nv_bfloat16, wmma::row_major> fah[2], fal[2];
                wmma::fragment<wmma::matrix_b, 16, 16, 16, __nv_bfloat16, wmma::col_major> fbh[2], fbl[2];
#pragma unroll
                for (int i = 0; i < 2; i++) {
                    wmma::load_matrix_sync(fah[i], &ah[(wm + i * 16) * ASTR + ks], ASTR);
                    wmma::load_matrix_sync(fal[i], &al[(wm + i * 16) * ASTR + ks], ASTR);
                }
#pragma unroll
                for (int j = 0; j < 2; j++) {
                    wmma::load_matrix_sync(fbh[j], &bh[(wn + j * 16) * ASTR + ks], ASTR);
                    wmma::load_matrix_sync(fbl[j], &bl[(wn + j * 16) * ASTR + ks], ASTR);
                }
#pragma unroll
                for (int i = 0; i < 2; i++)
#pragma unroll
                    for (int j = 0; j < 2; j++) {
                        wmma::mma_sync(acc[i][j], fah[i], fbh[j], acc[i][j]);
                        wmma::mma_sync(acc[i][j], fah[i], fbl[j], acc[i][j]);
                        wmma::mma_sync(acc[i][j], fal[i], fbh[j], acc[i][j]);
                    }
            }
        }

        if (more) {
            int nb = buf ^ 1;
            __nv_bfloat16* ah = (__nv_bfloat16*)(smem + nb * SM_BUF + SM_AH);
            __nv_bfloat16* al = (__nv_bfloat16*)(smem + nb * SM_BUF + SM_AL);
            __nv_bfloat16* bh = (__nv_bfloat16*)(smem + nb * SM_BUF + SM_BH);
            __nv_bfloat16* bl = (__nv_bfloat16*)(smem + nb * SM_BUF + SM_BL);
#pragma unroll
            for (int q = 0; q < 4; q++) {
                uint2 hv, lv; hilo4(va[q], hv, lv);
                *(uint2*)&ah[a_row * ASTR + a_cb + q * 4] = hv;
                *(uint2*)&al[a_row * ASTR + a_cb + q * 4] = lv;
            }
#pragma unroll
            for (int q = 0; q < 2; q++) {
                uint2 hv, lv; hilo4(vb[q], hv, lv);
                *(uint2*)&bh[b_row * ASTR + b_cb + q * 4] = hv;
                *(uint2*)&bl[b_row * ASTR + b_cb + q * 4] = lv;
            }
            __syncthreads();
            buf = nb;
        }
    }

    // epilogue: frags -> smem (reuse buffers) -> global
    __syncthreads();
    float* cs = (float*)smem;
#pragma unroll
    for (int i = 0; i < 2; i++)
#pragma unroll
        for (int j = 0; j < 2; j++)
            wmma::store_matrix_sync(&cs[(wm + i * 16) * CSTR + wn + j * 16],
                                    acc[i][j], CSTR, wmma::mem_row_major);
    __syncthreads();

    int e_row = tid >> 1;
    int e_cb = (tid & 1) * 32;
    int gm = m0 + e_row;
    if (mode == 2) {
        const float* bb = (blockIdx.z == 0) ? bias : nullptr;
#pragma unroll
        for (int c = 0; c < 32; c++) {
            int col = e_cb + c;
            if (col >= nt) break;
            float v = cs[e_row * CSTR + col];
            if (bb) v += bb[n0 + col];
            atomicAdd(&C[(size_t)gm * N + n0 + col], v);
        }
    } else {
        float* Cp = C + (mode == 1 ? (size_t)blockIdx.z * M * N : 0)
                    + (size_t)gm * N + n0;
#pragma unroll
        for (int c = 0; c < 32; c += 4) {
            int col = e_cb + c;
            if (col >= nt) break;
            float4 v = *(float4*)&cs[e_row * CSTR + col];
            if (bias) {
                float4 b = *(const float4*)(bias + n0 + col);
                v.x += b.x; v.y += b.y; v.z += b.z; v.w += b.w;
            }
            *(float4*)(Cp + col) = v;
        }
    }
}

// ---------------------------------------------------------------------------
// Causal depthwise conv (width 4) + SiLU -> u
// ---------------------------------------------------------------------------
__global__ void conv_silu_kernel(const float* __restrict__ xz,
                                 const float* __restrict__ cw,
                                 float* __restrict__ u) {
    int idx = blockIdx.x * blockDim.x + threadIdx.x;
    int t = idx >> 9;
    int d = idx & 511;
    int l = t & 511;
    float acc = 0.f;
#pragma unroll
    for (int j = 0; j < 4; j++) {
        int ll = l - 3 + j;
        if (ll >= 0) acc = fmaf(cw[d * 4 + j], xz[(size_t)(t - 3 + j) * XZW + d], acc);
    }
    u[idx] = acc / (1.f + __expf(-acc));
}

// ---------------------------------------------------------------------------
// Reduce split-K x-proj partials: xdbc = sum_z xdbc_p[z]
// ---------------------------------------------------------------------------
__global__ void xreduce_kernel(const float* __restrict__ xp,
                               float* __restrict__ xo) {
    int idx = blockIdx.x * blockDim.x + threadIdx.x;
    const int S = TT * RXW;
    xo[idx] = xp[idx] + xp[S + idx] + xp[2*S + idx] + xp[3*S + idx];
}

// ---------------------------------------------------------------------------
// delta = softplus(dt @ dt_w^T + dt_b)
// ---------------------------------------------------------------------------
__global__ void delta_kernel(const float* __restrict__ xdbc,
                             const float* __restrict__ dtw,
                             const float* __restrict__ dtb,
                             float* __restrict__ delta) {
    int idx = blockIdx.x * blockDim.x + threadIdx.x;
    int t = idx >> 9;
    int d = idx & 511;
    float s = dtb[d];
#pragma unroll
    for (int r = 0; r < DTR; r++) s = fmaf(xdbc[t * RXW + r], dtw[d * DTR + r], s);
    delta[idx] = (s > 20.f) ? s : log1pf(__expf(s));
}

// ---------------------------------------------------------------------------
// Chunked scan pass A: per (b,d,n,chunk) compute prod(a) and h_end from 0.
// ---------------------------------------------------------------------------
__global__ void scanA_kernel(const float* __restrict__ delta,
                             const float* __restrict__ u,
                             const float* __restrict__ xdbc,
                             const float* __restrict__ A_log,
                             float* __restrict__ ap_out,
                             float* __restrict__ he_out) {
    int bi = blockIdx.x;
    int c = bi & (NCH - 1);
    int dg = (bi >> 3) & 31;
    int b = bi >> 8;
    int n = threadIdx.x & 15;
    int d = (dg << 4) + (threadIdx.x >> 4);
    int tbase = (b << 9) + c * CHL;

    float Ac = -__expf(A_log[d * DS + n]);
    const float* pd = delta + (size_t)tbase * DI + d;
    const float* pu = u + (size_t)tbase * DI + d;
    const float* px = xdbc + (size_t)tbase * RXW + 16 + n;

    float h = 0.f, ap = 1.f;
#pragma unroll 4
    for (int l = 0; l < CHL; l++) {
        float del = pd[(size_t)l * DI];
        float uu = pu[(size_t)l * DI];
        float Bn = px[l * RXW];
        float a = __expf(del * Ac);
        h = fmaf(a, h, del * uu * Bn);
        ap *= a;
    }
    int idx = ((b * DI + d) << 4) + n;
    ap_out[c * CARRY + idx] = ap;
    he_out[c * CARRY + idx] = h;
}

// ---------------------------------------------------------------------------
// Chunked scan pass B: fold carries, replay chunk, reduce y over n, gate.
// ---------------------------------------------------------------------------
__global__ void scanB_kernel(const float* __restrict__ delta,
                             const float* __restrict__ u,
                             const float* __restrict__ xdbc,
                             const float* __restrict__ A_log,
                             const float* __restrict__ xz,
                             const float* __restrict__ Dp,
                             const float* __restrict__ ap_in,
                             const float* __restrict__ he_in,
                             float* __restrict__ yg) {
    int bi = blockIdx.x;
    int c = bi & (NCH - 1);
    int dg = (bi >> 3) & 31;
    int b = bi >> 8;
    int n = threadIdx.x & 15;
    int d = (dg << 4) + (threadIdx.x >> 4);
    int tbase = (b << 9) + c * CHL;

    float Ac = -__expf(A_log[d * DS + n]);
    float Dv = Dp[d];

    int idx = ((b * DI + d) << 4) + n;
    float h = 0.f;
    for (int j = 0; j < c; j++)
        h = fmaf(ap_in[j * CARRY + idx], h, he_in[j * CARRY + idx]);

    const float* pd = delta + (size_t)tbase * DI + d;
    const float* pu = u + (size_t)tbase * DI + d;
    const float* px = xdbc + (size_t)tbase * RXW;
    const float* pz = xz + (size_t)tbase * XZW + DI + d;
    float* py = yg + (size_t)tbase * DI + d;

#pragma unroll 4
    for (int l = 0; l < CHL; l++) {
        float del = pd[(size_t)l * DI];
        float uu = pu[(size_t)l * DI];
        float Bn = px[l * RXW + 16 + n];
        float Cn = px[l * RXW + 32 + n];
        float a = __expf(del * Ac);
        h = fmaf(a, h, del * uu * Bn);
        float yp = h * Cn;
#pragma unroll
        for (int o = 8; o > 0; o >>= 1)
            yp += __shfl_xor_sync(0xffffffffu, yp, o, 16);
        if (n == 0) {
            float z = pz[(size_t)l * XZW];
            float sz = z / (1.f + __expf(-z));
            py[(size_t)l * DI] = (yp + uu * Dv) * sz;
        }
    }
}

// ---------------------------------------------------------------------------
// Host launcher
// ---------------------------------------------------------------------------
extern "C" void kernel_launch(void* const* d_in, const int* in_sizes, int n_in,
                              void* d_out, int out_size) {
    const float* x      = (const float*)d_in[0];
    const float* norm_w = (const float*)d_in[1];
    const float* W_in   = (const float*)d_in[2];
    const float* b_in   = (const float*)d_in[3];
    const float* conv_w = (const float*)d_in[4];
    const float* W_x    = (const float*)d_in[5];
    const float* dt_w   = (const float*)d_in[6];
    const float* dt_b   = (const float*)d_in[7];
    const float* A_log  = (const float*)d_in[8];
    const float* Dp     = (const float*)d_in[9];
    const float* W_out  = (const float*)d_in[10];
    const float* b_out  = (const float*)d_in[11];
    float* xcur = (float*)d_out;

    float *scale, *xz, *u, *xdbc_p, *xdbc, *delta, *ap, *he, *yg;
    cudaGetSymbolAddress((void**)&scale, g_scale);
    cudaGetSymbolAddress((void**)&xz, g_xz);
    cudaGetSymbolAddress((void**)&u, g_u);
    cudaGetSymbolAddress((void**)&xdbc_p, g_xdbc_p);
    cudaGetSymbolAddress((void**)&xdbc, g_xdbc);
    cudaGetSymbolAddress((void**)&delta, g_delta);
    cudaGetSymbolAddress((void**)&ap, g_ap);
    cudaGetSymbolAddress((void**)&he, g_he);
    cudaGetSymbolAddress((void**)&yg, g_yg);

    cudaFuncSetAttribute(tc_gemm_kernel,
                         cudaFuncAttributeMaxDynamicSharedMemorySize, SM_TOTAL);

    cudaMemcpyAsync(xcur, x, (size_t)TT * DM * sizeof(float),
                    cudaMemcpyDeviceToDevice);

    const int ew_blocks = (TT * DI) / 256;      // 4096
    const int xr_blocks = (TT * RXW) / 256;     // 384
    const int sc_blocks = BB * 32 * NCH;        // 1024

    for (int i = 0; i < NL; i++) {
        rms_scale_kernel<<<TT / 8, 256>>>(xcur, scale);

        tc_gemm_kernel<<<dim3(XZW / 64, TT / 128, 1), 256, SM_TOTAL>>>(
            xcur, W_in + (size_t)i * XZW * DM, b_in + (size_t)i * XZW,
            scale, norm_w + (size_t)i * DM,
            xz, TT, XZW, DM, DM, /*mode=*/0);

        conv_silu_kernel<<<ew_blocks, 256>>>(xz, conv_w + (size_t)i * DI * DC, u);

        tc_gemm_kernel<<<dim3(1, TT / 128, XSPLIT), 256, SM_TOTAL>>>(
            u, W_x + (size_t)i * RXW * DI, nullptr, nullptr, nullptr,
            xdbc_p, TT, RXW, DI, DI / XSPLIT, /*mode=*/1);

        xreduce_kernel<<<xr_blocks, 256>>>(xdbc_p, xdbc);

        delta_kernel<<<ew_blocks, 256>>>(xdbc, dt_w + (size_t)i * DI * DTR,
                                         dt_b + (size_t)i * DI, delta);

        scanA_kernel<<<sc_blocks, 256>>>(delta, u, xdbc,
                                         A_log + (size_t)i * DI * DS, ap, he);

        scanB_kernel<<<sc_blocks, 256>>>(delta, u, xdbc,
                                         A_log + (size_t)i * DI * DS,
                                         xz, Dp + (size_t)i * DI,
                                         ap, he, yg);

        tc_gemm_kernel<<<dim3(DM / 64, TT / 128, 2), 256, SM_TOTAL>>>(
            yg, W_out + (size_t)i * DM * DI, b_out + (size_t)i * DM,
            nullptr, nullptr,
            xcur, TT, DM, DI, DI / 2, /*mode=*/2);
    }
}